// round 5
// baseline (speedup 1.0000x reference)
#include <cuda_runtime.h>
#include <math.h>

#define BB   256

// out layout: value [B,32,32,32] | weight [B,32,32] | wp [B,32,32]
#define WOFF      (8388608ull)
#define WPOFF     (8650752ull)

typedef unsigned long long ull;

// Scratch (device globals; all weight forms duplicated into both f32x2 halves)
__device__ __align__(16) ull g_Md  [128 * 128];   // (Wq Wk^T) dup'd
__device__ __align__(16) ull g_Mpd [128 * 128];   // (Wqp Wkp^T) dup'd
__device__ __align__(16) ull g_Wvd [128 * 128];
__device__ __align__(16) ull g_Wvpd[128 * 128];
__device__ __align__(16) ull g_Wf1d[256 * 64];
__device__ float g_U[BB * 32 * 64];
__device__ float g_V[BB * 32 * 64];

// ---- packed f32x2 helpers ----
__device__ __forceinline__ ull pk2(float v) {
    ull r; asm("mov.b64 %0, {%1, %1};" : "=l"(r) : "f"(v)); return r;
}
__device__ __forceinline__ ull pk2two(float a, float b) {
    ull r; asm("mov.b64 %0, {%1, %2};" : "=l"(r) : "f"(a), "f"(b)); return r;
}
__device__ __forceinline__ ull ffma2(ull a, ull b, ull c) {
    ull d; asm("fma.rn.f32x2 %0, %1, %2, %3;" : "=l"(d) : "l"(a), "l"(b), "l"(c)); return d;
}
__device__ __forceinline__ ull mul2(ull a, ull b) {
    ull d; asm("mul.rn.f32x2 %0, %1, %2;" : "=l"(d) : "l"(a), "l"(b)); return d;
}
__device__ __forceinline__ float2 upk2(ull v) {
    float2 f; asm("mov.b64 {%0, %1}, %2;" : "=f"(f.x), "=f"(f.y) : "l"(v)); return f;
}

__device__ __forceinline__ float warp_max(float v) {
    #pragma unroll
    for (int o = 16; o; o >>= 1) v = fmaxf(v, __shfl_xor_sync(0xffffffffu, v, o));
    return v;
}
__device__ __forceinline__ float warp_sum(float v) {
    #pragma unroll
    for (int o = 16; o; o >>= 1) v += __shfl_xor_sync(0xffffffffu, v, o);
    return v;
}

// ---------------------------------------------------------------------------
// Kernel 0: blocks 0..63: M/Mp GEMMs (dup'd output). blocks 64..111: weight dup copies.
// ---------------------------------------------------------------------------
__global__ void k0_precompute(const float* __restrict__ Wq, const float* __restrict__ Wk,
                              const float* __restrict__ Wqp, const float* __restrict__ Wkp,
                              const float* __restrict__ Wv, const float* __restrict__ Wvp,
                              const float* __restrict__ Wf1) {
    __shared__ float sA[8 * 128];
    __shared__ float sB[64 * 129];
    const int bx = blockIdx.x;
    const int t  = threadIdx.x;

    if (bx >= 64) {
        // dup copies: Wv (16384), Wvp (16384), Wf1 (256*64=16384)
        int gi = (bx - 64) * 256 + t;           // 0..12287
        #pragma unroll
        for (int k = 0; k < 4; ++k) {
            int idx = gi + k * 12288;           // covers 49152
            float v; ull* dst;
            if (idx < 16384)       { v = Wv [idx];          dst = &g_Wvd [idx]; }
            else if (idx < 32768)  { v = Wvp[idx - 16384];  dst = &g_Wvpd[idx - 16384]; }
            else                   { v = Wf1[idx - 32768];  dst = &g_Wf1d[idx - 32768]; }
            *dst = pk2(v);
        }
        return;
    }

    const int mat = bx >> 5;                    // 0: M, 1: Mp
    const int e0  = (bx & 15) * 8;
    const int c0  = ((bx >> 4) & 1) * 64;
    const float* A  = mat ? Wqp : Wq;
    const float* Bm = mat ? Wkp : Wk;
    ull* outd       = mat ? g_Mpd : g_Md;

    for (int idx = t; idx < 1024; idx += 256) sA[idx] = A[e0 * 128 + idx];
    for (int idx = t; idx < 64 * 128; idx += 256) {
        int r = idx >> 7, d = idx & 127;
        sB[r * 129 + d] = Bm[(c0 + r) * 128 + d];
    }
    __syncthreads();
    const int w = t >> 5, l = t & 31;
    float a0 = 0.f, a1 = 0.f;
    #pragma unroll 8
    for (int d = 0; d < 128; ++d) {
        float av = sA[w * 128 + d];
        a0 = fmaf(av, sB[l * 129 + d], a0);
        a1 = fmaf(av, sB[(l + 32) * 129 + d], a1);
    }
    outd[(e0 + w) * 128 + c0 + l]      = pk2(a0);
    outd[(e0 + w) * 128 + c0 + 32 + l] = pk2(a1);
}

// ---------------------------------------------------------------------------
// Packed GEMM cores. X packed: Xp[f][p] = (X[2p][f], X[2p+1][f]), row stride 17 ull.
// Warp w owns pairs 2w, 2w+1 (rows 4w..4w+3). Lane l owns cols 4l..4l+3 (128-wide)
// or cols 2l..2l+1 (64-wide). W arrays are dup'd (ull per scalar).
// ---------------------------------------------------------------------------
template <int K>
__device__ __forceinline__ void mm_accP(const ull* __restrict__ Xp,
                                        const ull* __restrict__ Wd,
                                        ull acc[2][4], int w, int l) {
    #pragma unroll 4
    for (int e = 0; e < K; ++e) {
        ull x0 = Xp[e * 17 + 2 * w];
        ull x1 = Xp[e * 17 + 2 * w + 1];
        ulonglong2 wv0 = *reinterpret_cast<const ulonglong2*>(&Wd[e * 128 + 4 * l]);
        ulonglong2 wv1 = *reinterpret_cast<const ulonglong2*>(&Wd[e * 128 + 4 * l + 2]);
        acc[0][0] = ffma2(x0, wv0.x, acc[0][0]);
        acc[0][1] = ffma2(x0, wv0.y, acc[0][1]);
        acc[0][2] = ffma2(x0, wv1.x, acc[0][2]);
        acc[0][3] = ffma2(x0, wv1.y, acc[0][3]);
        acc[1][0] = ffma2(x1, wv0.x, acc[1][0]);
        acc[1][1] = ffma2(x1, wv0.y, acc[1][1]);
        acc[1][2] = ffma2(x1, wv1.x, acc[1][2]);
        acc[1][3] = ffma2(x1, wv1.y, acc[1][3]);
    }
}

// store acc (plain, no act) into packed buffer: Yp[f][pair]
__device__ __forceinline__ void storeP(ull* __restrict__ Yp, ull acc[2][4], int w, int l) {
    #pragma unroll
    for (int q = 0; q < 2; ++q)
        #pragma unroll
        for (int c = 0; c < 4; ++c)
            Yp[(4 * l + c) * 17 + 2 * w + q] = acc[q][c];
}

// store tanh(acc) into packed buffer
__device__ __forceinline__ void storeP_tanh(ull* __restrict__ Yp, ull acc[2][4], int w, int l) {
    #pragma unroll
    for (int q = 0; q < 2; ++q)
        #pragma unroll
        for (int c = 0; c < 4; ++c) {
            float2 p = upk2(acc[q][c]);
            Yp[(4 * l + c) * 17 + 2 * w + q] = pk2two(tanhf(p.x), tanhf(p.y));
        }
}

// acc64[q][c] += Xp[32 rows, 128] @ Wd64[128][64], lane cols 2l..2l+1
__device__ __forceinline__ void mm64P(const ull* __restrict__ Xp,
                                      const ull* __restrict__ Wd64,
                                      ull acc[2][2], int w, int l) {
    #pragma unroll 4
    for (int e = 0; e < 128; ++e) {
        ull x0 = Xp[e * 17 + 2 * w];
        ull x1 = Xp[e * 17 + 2 * w + 1];
        ulonglong2 wv = *reinterpret_cast<const ulonglong2*>(&Wd64[e * 64 + 2 * l]);
        acc[0][0] = ffma2(x0, wv.x, acc[0][0]);
        acc[0][1] = ffma2(x0, wv.y, acc[0][1]);
        acc[1][0] = ffma2(x1, wv.x, acc[1][0]);
        acc[1][1] = ffma2(x1, wv.y, acc[1][1]);
    }
}

// unpack acc64 (rows in halves) into plain [row][64] smem
__device__ __forceinline__ void store64_plain(float* __restrict__ Y, ull acc[2][2],
                                              int w, int l) {
    #pragma unroll
    for (int q = 0; q < 2; ++q)
        #pragma unroll
        for (int c = 0; c < 2; ++c) {
            float2 p = upk2(acc[q][c]);
            Y[(4 * w + 2 * q)     * 64 + 2 * l + c] = p.x;
            Y[(4 * w + 2 * q + 1) * 64 + 2 * l + c] = p.y;
        }
}

// ---------------------------------------------------------------------------
// Kernel 1: one block per batch. smem = 76,928 B -> 3 blocks/SM.
// ---------------------------------------------------------------------------
#define SM1_BYTES 76928
#define SOFTMAX_SCALE 0.08838834764831843f   // 1/sqrt(128)

extern "C" __global__ void __launch_bounds__(256, 3)
k1_batch(const float* __restrict__ states, const float* __restrict__ policies,
         const float* __restrict__ actions, const float* __restrict__ states_people,
         const float* __restrict__ actions_people, float* __restrict__ out) {
    extern __shared__ __align__(16) ull smu[];
    ull*   s_oaP  = smu;                 // [128][17] packed oa
    ull*   s_oapP = s_oaP + 2176;        // [128][17] packed oap
    ull*   s_tP   = s_oapP + 2176;       // [128][17] packed t/tp/va/vp/avp (warp-local pairs)
    float* s_w    = reinterpret_cast<float*>(s_tP + 2176);   // 32 x 32
    float* s_wp   = s_w  + 1024;         // 32 x 33
    float* s_A1   = s_wp + 1056;         // 32 x 64 (early: sc 32x33)
    float* s_C1   = s_A1 + 2048;         // 32 x 64 (early: sp 32x33)
    float* s_sc   = s_A1;
    float* s_sp   = s_C1;
    float* s_oaF  = reinterpret_cast<float*>(s_oaP);
    float* s_oapF = reinterpret_cast<float*>(s_oapP);

    const int b = blockIdx.x;
    const int t = threadIdx.x;
    const int w = t >> 5, l = t & 31;

    const float* ac = actions  + (size_t)b * 1024;
    const float* po = policies + (size_t)b * 1024;

    // --- delta (pol - act) packed rows, warp-local pairs: dp[q] = (d[4w+2q][l], d[4w+2q+1][l])
    ull dp[2];
    #pragma unroll
    for (int q = 0; q < 2; ++q) {
        float d0 = po[(4 * w + 2 * q) * 32 + l]     - ac[(4 * w + 2 * q) * 32 + l];
        float d1 = po[(4 * w + 2 * q + 1) * 32 + l] - ac[(4 * w + 2 * q + 1) * 32 + l];
        dp[q] = pk2two(d0, d1);
    }

    // --- load inputs -> packed smem (coalesced gmem reads; 2-way STS conflicts) ---
    {
        const float* st  = states         + (size_t)b * 32 * 96;
        const float* stp = states_people  + (size_t)b * 32 * 96;
        const float* acp = actions_people + (size_t)b * 1024;
        for (int idx = t; idx < 4096; idx += 256) {
            int i = idx >> 7, c = idx & 127;
            float voa = (c < 96) ? st [i * 96 + c] : ac [i * 32 + c - 96];
            float vop = (c < 96) ? stp[i * 96 + c] : acp[i * 32 + c - 96];
            int fidx = (c * 17 + (i >> 1)) * 2 + (i & 1);
            s_oaF [fidx] = voa;
            s_oapF[fidx] = vop;
        }
    }
    __syncthreads();   // S1

    // --- t = oa@M -> scores ; tp = oa@Mp -> scores_p ---
    {
        ull a1[2][4] = {{0,0,0,0},{0,0,0,0}};
        mm_accP<128>(s_oaP, g_Md, a1, w, l);
        storeP(s_tP, a1, w, l);
        ull sc01 = 0, sc23 = 0;
        #pragma unroll 4
        for (int f = 0; f < 128; ++f) {
            ull t0 = s_tP[f * 17 + 2 * w];
            ull t1 = s_tP[f * 17 + 2 * w + 1];
            ull oo = pk2(s_oaF[(f * 17 + (l >> 1)) * 2 + (l & 1)]);
            sc01 = ffma2(t0, oo, sc01);
            sc23 = ffma2(t1, oo, sc23);
        }
        {
            float2 p0 = upk2(sc01), p1 = upk2(sc23);
            s_sc[(4 * w + 0) * 33 + l] = p0.x;
            s_sc[(4 * w + 1) * 33 + l] = p0.y;
            s_sc[(4 * w + 2) * 33 + l] = p1.x;
            s_sc[(4 * w + 3) * 33 + l] = p1.y;
        }

        ull a2[2][4] = {{0,0,0,0},{0,0,0,0}};
        mm_accP<128>(s_oaP, g_Mpd, a2, w, l);
        storeP(s_tP, a2, w, l);
        ull cp01 = 0, cp23 = 0;
        #pragma unroll 4
        for (int f = 0; f < 128; ++f) {
            ull t0 = s_tP[f * 17 + 2 * w];
            ull t1 = s_tP[f * 17 + 2 * w + 1];
            ull oo = pk2(s_oapF[(f * 17 + (l >> 1)) * 2 + (l & 1)]);
            cp01 = ffma2(t0, oo, cp01);
            cp23 = ffma2(t1, oo, cp23);
        }
        {
            float2 p0 = upk2(cp01), p1 = upk2(cp23);
            s_sp[(4 * w + 0) * 33 + l] = p0.x;
            s_sp[(4 * w + 1) * 33 + l] = p0.y;
            s_sp[(4 * w + 2) * 33 + l] = p1.x;
            s_sp[(4 * w + 3) * 33 + l] = p1.y;
        }
    }
    __syncthreads();   // S2

    // --- column softmaxes ---
    {
        #pragma unroll
        for (int k = 0; k < 4; ++k) {
            int a = w + 8 * k;
            float v  = s_sc[l * 33 + a] * SOFTMAX_SCALE;
            float m  = warp_max(v);
            float e  = expf(v - m);
            float s  = warp_sum(e);
            float wg = e / s;
            s_w[a * 32 + l] = wg;
            out[WOFF + ((size_t)b * 32 + a) * 32 + l] = wg;
            float v2 = s_sp[l * 33 + a] * SOFTMAX_SCALE;
            float m2 = warp_max(v2);
            float e2 = expf(v2 - m2);
            float s2 = warp_sum(e2);
            s_wp[l * 33 + a] = e2 / s2;
        }
    }
    __syncthreads();   // S3 (frees sc/sp for A1/C1)

    // --- va -> A1 ; vp -> V(gmem) ; avp -> C1 (warp-private chains) ---
    {
        ull av[2][4] = {{0,0,0,0},{0,0,0,0}};
        mm_accP<128>(s_oaP, g_Wvd, av, w, l);
        storeP_tanh(s_tP, av, w, l);                    // va packed
        ull a1acc[2][2] = {{0,0},{0,0}};
        mm64P(s_tP, g_Wf1d, a1acc, w, l);               // A1 (kept in regs)
        store64_plain(s_A1, a1acc, w, l);

        // vp = tanh(va_pre + (pol-act) @ Wv[96:,:])
        #pragma unroll 4
        for (int e = 0; e < 32; ++e) {
            ull x0 = __shfl_sync(0xffffffffu, dp[0], e);
            ull x1 = __shfl_sync(0xffffffffu, dp[1], e);
            ulonglong2 wv0 = *reinterpret_cast<const ulonglong2*>(&g_Wvd[(96 + e) * 128 + 4 * l]);
            ulonglong2 wv1 = *reinterpret_cast<const ulonglong2*>(&g_Wvd[(96 + e) * 128 + 4 * l + 2]);
            av[0][0] = ffma2(x0, wv0.x, av[0][0]);
            av[0][1] = ffma2(x0, wv0.y, av[0][1]);
            av[0][2] = ffma2(x0, wv1.x, av[0][2]);
            av[0][3] = ffma2(x0, wv1.y, av[0][3]);
            av[1][0] = ffma2(x1, wv0.x, av[1][0]);
            av[1][1] = ffma2(x1, wv0.y, av[1][1]);
            av[1][2] = ffma2(x1, wv1.x, av[1][2]);
            av[1][3] = ffma2(x1, wv1.y, av[1][3]);
        }
        storeP_tanh(s_tP, av, w, l);                    // vp packed
        ull vacc[2][2] = {{0,0},{0,0}};
        mm64P(s_tP, g_Wf1d, vacc, w, l);                // vp @ W1_top

        // V = (vacc - a1acc) / 32 -> gmem
        {
            const ull cpos = pk2(0.03125f);
            const ull cneg = pk2(-0.03125f);
            float* gV = g_V + (size_t)b * 2048;
            #pragma unroll
            for (int q = 0; q < 2; ++q) {
                ull v0 = ffma2(a1acc[q][0], cneg, mul2(vacc[q][0], cpos));
                ull v1 = ffma2(a1acc[q][1], cneg, mul2(vacc[q][1], cpos));
                float2 p0 = upk2(v0), p1 = upk2(v1);
                *reinterpret_cast<float2*>(&gV[(4 * w + 2 * q)     * 64 + 2 * l]) =
                    make_float2(p0.x, p1.x);
                *reinterpret_cast<float2*>(&gV[(4 * w + 2 * q + 1) * 64 + 2 * l]) =
                    make_float2(p0.y, p1.y);
            }
        }

        // avp -> C1
        ull ap[2][4] = {{0,0,0,0},{0,0,0,0}};
        mm_accP<128>(s_oapP, g_Wvpd, ap, w, l);
        storeP_tanh(s_tP, ap, w, l);
        ull c1acc[2][2] = {{0,0},{0,0}};
        mm64P(s_tP, g_Wf1d + 128 * 64, c1acc, w, l);
        store64_plain(s_C1, c1acc, w, l);
    }
    __syncthreads();   // S4

    // --- wp to global ---
    for (int idx = t; idx < 1024; idx += 256)
        out[WPOFF + (size_t)b * 1024 + idx] = s_wp[(idx >> 5) * 33 + (idx & 31)];

    // --- U[a, 2l..2l+1] = (w[a,:]@A1 + wp[a,:]@C1)/32, warp rows 4w..4w+3 ---
    {
        const int r0 = 4 * w;
        const ull* A1u = reinterpret_cast<const ull*>(s_A1);
        const ull* C1u = reinterpret_cast<const ull*>(s_C1);
        ull uacc[4] = {0, 0, 0, 0};
        #pragma unroll 4
        for (int j = 0; j < 32; ++j) {
            ull wv = A1u[j * 32 + l];
            #pragma unroll
            for (int r = 0; r < 4; ++r)
                uacc[r] = ffma2(pk2(s_w[(r0 + r) * 32 + j]), wv, uacc[r]);
        }
        #pragma unroll 4
        for (int p = 0; p < 32; ++p) {
            ull wv = C1u[p * 32 + l];
            #pragma unroll
            for (int r = 0; r < 4; ++r)
                uacc[r] = ffma2(pk2(s_wp[(r0 + r) * 33 + p]), wv, uacc[r]);
        }
        float* gU = g_U + (size_t)b * 2048;
        #pragma unroll
        for (int r = 0; r < 4; ++r) {
            float2 p = upk2(uacc[r]);
            *reinterpret_cast<float2*>(&gU[(r0 + r) * 64 + 2 * l]) =
                make_float2(p.x * 0.03125f, p.y * 0.03125f);
        }
    }
}

// ---------------------------------------------------------------------------
// Kernel 2 (unchanged, round-2 proven): value = lrelu(U + weight*V) @ W_f2
// ---------------------------------------------------------------------------
extern "C" __global__ void __launch_bounds__(256)
k2_value(const float* __restrict__ Wf2, float* __restrict__ out) {
    __shared__ float sU [8 * 64];
    __shared__ float sV [32 * 65];
    __shared__ __align__(16) float sW2[64 * 32];
    __shared__ float sW [8 * 33];
    const int t  = threadIdx.x;
    const int b  = blockIdx.x >> 2;
    const int a0 = (blockIdx.x & 3) * 8;

    for (int idx = t; idx < 2048; idx += 256) {
        int i = idx >> 6, f = idx & 63;
        sV[i * 65 + f] = g_V[(size_t)b * 2048 + idx];
    }
    for (int idx = t; idx < 512; idx += 256)
        sU[idx] = g_U[(size_t)b * 2048 + a0 * 64 + idx];
    for (int idx = t; idx < 2048; idx += 256) sW2[idx] = Wf2[idx];
    {
        int a = t >> 5, i = t & 31;
        sW[a * 33 + i] = out[WOFF + ((size_t)b * 32 + a0 + a) * 32 + i];
    }
    __syncthreads();

    const int w = t >> 5, l = t & 31;
    const float wai = sW[w * 33 + l];
    const float* Ua = &sU[w * 64];
    ull acc[16];
    #pragma unroll
    for (int q = 0; q < 16; ++q) acc[q] = 0ull;

    #pragma unroll 8
    for (int f = 0; f < 64; ++f) {
        float h = fmaf(wai, sV[l * 65 + f], Ua[f]);
        h = fmaxf(h, 0.f) + 0.01f * fminf(h, 0.f);       // leaky_relu(0.01)
        ull hh = pk2(h);
        const ulonglong2* row = reinterpret_cast<const ulonglong2*>(&sW2[f * 32]);
        #pragma unroll
        for (int q = 0; q < 8; ++q) {
            ulonglong2 wv = row[q];
            acc[2 * q]     = ffma2(hh, wv.x, acc[2 * q]);
            acc[2 * q + 1] = ffma2(hh, wv.y, acc[2 * q + 1]);
        }
    }
    float4* op = reinterpret_cast<float4*>(out + (((size_t)b * 32 + a0 + w) * 32 + l) * 32);
    #pragma unroll
    for (int q = 0; q < 8; ++q) {
        float2 p0 = upk2(acc[2 * q]);
        float2 p1 = upk2(acc[2 * q + 1]);
        op[q] = make_float4(p0.x, p0.y, p1.x, p1.y);
    }
}

// ---------------------------------------------------------------------------
extern "C" void kernel_launch(void* const* d_in, const int* in_sizes, int n_in,
                              void* d_out, int out_size) {
    const float* states         = (const float*)d_in[0];
    const float* policies       = (const float*)d_in[1];
    const float* actions        = (const float*)d_in[2];
    const float* states_people  = (const float*)d_in[3];
    const float* actions_people = (const float*)d_in[4];
    const float* Wk  = (const float*)d_in[5];
    const float* Wq  = (const float*)d_in[6];
    const float* Wv  = (const float*)d_in[7];
    const float* Wkp = (const float*)d_in[8];
    const float* Wqp = (const float*)d_in[9];
    const float* Wvp = (const float*)d_in[10];
    const float* Wf1 = (const float*)d_in[11];
    const float* Wf2 = (const float*)d_in[12];
    float* out = (float*)d_out;

    k0_precompute<<<112, 256>>>(Wq, Wk, Wqp, Wkp, Wv, Wvp, Wf1);

    cudaFuncSetAttribute(k1_batch, cudaFuncAttributeMaxDynamicSharedMemorySize, SM1_BYTES);
    k1_batch<<<256, 256, SM1_BYTES>>>(states, policies, actions,
                                      states_people, actions_people, out);

    k2_value<<<1024, 256>>>(Wf2, out);
}

// round 6
// speedup vs baseline: 1.3650x; 1.3650x over previous
#include <cuda_runtime.h>
#include <math.h>

#define BB   256

// out layout: value [B,32,32,32] | weight [B,32,32] | wp [B,32,32]
#define WOFF      (8388608ull)
#define WPOFF     (8650752ull)

typedef unsigned long long ull;

__device__ float g_M [128 * 128];
__device__ float g_Mp[128 * 128];
__device__ float g_U [BB * 32 * 64];
__device__ float g_V [BB * 32 * 64];

// ---- packed f32x2 helpers ----
__device__ __forceinline__ ull pk2(float v) {
    ull r; asm("mov.b64 %0, {%1, %1};" : "=l"(r) : "f"(v)); return r;
}
__device__ __forceinline__ ull ffma2(ull a, ull b, ull c) {
    ull d; asm("fma.rn.f32x2 %0, %1, %2, %3;" : "=l"(d) : "l"(a), "l"(b), "l"(c)); return d;
}
__device__ __forceinline__ float2 upk2(ull v) {
    float2 f; asm("mov.b64 {%0, %1}, %2;" : "=f"(f.x), "=f"(f.y) : "l"(v)); return f;
}

__device__ __forceinline__ float warp_max(float v) {
    #pragma unroll
    for (int o = 16; o; o >>= 1) v = fmaxf(v, __shfl_xor_sync(0xffffffffu, v, o));
    return v;
}
__device__ __forceinline__ float warp_sum(float v) {
    #pragma unroll
    for (int o = 16; o; o >>= 1) v += __shfl_xor_sync(0xffffffffu, v, o);
    return v;
}

// ---------------------------------------------------------------------------
// Kernel 0 (round-4 proven): M = W_q @ W_k^T, Mp = W_qp @ W_kp^T
// ---------------------------------------------------------------------------
__global__ void k0_precompute(const float* __restrict__ Wq, const float* __restrict__ Wk,
                              const float* __restrict__ Wqp, const float* __restrict__ Wkp) {
    __shared__ float sA[8 * 128];
    __shared__ float sB[64 * 129];
    const float* A  = blockIdx.z ? Wqp : Wq;
    const float* Bm = blockIdx.z ? Wkp : Wk;
    float* out      = blockIdx.z ? g_Mp : g_M;
    const int e0 = blockIdx.x * 8;
    const int c0 = blockIdx.y * 64;
    const int t  = threadIdx.x;
    for (int idx = t; idx < 1024; idx += 256) sA[idx] = A[e0 * 128 + idx];
    for (int idx = t; idx < 64 * 128; idx += 256) {
        int r = idx >> 7, d = idx & 127;
        sB[r * 129 + d] = Bm[(c0 + r) * 128 + d];
    }
    __syncthreads();
    const int w = t >> 5, l = t & 31;
    float a0 = 0.f, a1 = 0.f;
    #pragma unroll 8
    for (int d = 0; d < 128; ++d) {
        float av = sA[w * 128 + d];
        a0 = fmaf(av, sB[l * 129 + d], a0);
        a1 = fmaf(av, sB[(l + 32) * 129 + d], a1);
    }
    out[(e0 + w) * 128 + c0 + l]      = a0;
    out[(e0 + w) * 128 + c0 + 32 + l] = a1;
}

// ---------------------------------------------------------------------------
// Staged GEMM cores. Weights live in a 4096-float smem chunk buffer.
// Warp w owns rows r0=4w..4w+3.
// ---------------------------------------------------------------------------

// 32 e-rows x 128 cols chunk: lane l -> cols 4l..4l+3
__device__ __forceinline__ void mm_chunk128(const float* __restrict__ X, int xstr, int e0,
                                            const float* __restrict__ Ws,
                                            ull acc[4][2], int r0, int l) {
    #pragma unroll 4
    for (int e = 0; e < 32; ++e) {
        ulonglong2 wv = *reinterpret_cast<const ulonglong2*>(&Ws[e * 128 + 4 * l]);
        #pragma unroll
        for (int r = 0; r < 4; ++r) {
            ull xx = pk2(X[(r0 + r) * xstr + e0 + e]);
            acc[r][0] = ffma2(xx, wv.x, acc[r][0]);
            acc[r][1] = ffma2(xx, wv.y, acc[r][1]);
        }
    }
}

// 64 e-rows x 64 cols chunk: lane l -> cols 2l..2l+1
__device__ __forceinline__ void mm_chunk64(const float* __restrict__ X, int e0,
                                           const float* __restrict__ Ws,
                                           ull acc[4], int r0, int l) {
    #pragma unroll 4
    for (int e = 0; e < 64; ++e) {
        ull wv = *reinterpret_cast<const ull*>(&Ws[e * 64 + 2 * l]);
        #pragma unroll
        for (int r = 0; r < 4; ++r)
            acc[r] = ffma2(pk2(X[(r0 + r) * 128 + e0 + e]), wv, acc[r]);
    }
}

__device__ __forceinline__ void store128(float* __restrict__ Y, ull acc[4][2],
                                         int r0, int l, bool do_tanh) {
    #pragma unroll
    for (int r = 0; r < 4; ++r) {
        float2 p0 = upk2(acc[r][0]);
        float2 p1 = upk2(acc[r][1]);
        float4 v = make_float4(p0.x, p0.y, p1.x, p1.y);
        if (do_tanh) { v.x = tanhf(v.x); v.y = tanhf(v.y); v.z = tanhf(v.z); v.w = tanhf(v.w); }
        *reinterpret_cast<float4*>(&Y[(r0 + r) * 128 + 4 * l]) = v;
    }
}

// ---------------------------------------------------------------------------
// Kernel 1: one block per batch. smem = 90,496 B -> 2 blocks/SM.
// ---------------------------------------------------------------------------
#define SM1_BYTES 90496
#define SOFTMAX_SCALE 0.08838834764831843f   // 1/sqrt(128)

// stage 4096 floats from gmem into the chunk buffer (with enclosing syncs)
#define STAGE(SRC) do {                                                    \
    __syncthreads();                                                       \
    { const float4* s4 = reinterpret_cast<const float4*>(SRC);            \
      float4* d4 = reinterpret_cast<float4*>(s_Wst);                      \
      for (int i = t; i < 1024; i += 256) d4[i] = s4[i]; }                \
    __syncthreads();                                                       \
} while (0)

extern "C" __global__ void __launch_bounds__(256, 2)
k1_batch(const float* __restrict__ states, const float* __restrict__ policies,
         const float* __restrict__ actions, const float* __restrict__ states_people,
         const float* __restrict__ actions_people,
         const float* __restrict__ Wv, const float* __restrict__ Wvp,
         const float* __restrict__ Wf1, float* __restrict__ out) {
    extern __shared__ __align__(16) float sm[];
    float* s_oa  = sm;                 // 32 x 129
    float* s_oap = s_oa  + 4128;       // 32 x 129
    float* s_t   = s_oap + 4128;       // 32 x 128  (t/tp/va/vp/avp rows, warp-local)
    float* s_w   = s_t   + 4096;       // 32 x 32
    float* s_wp  = s_w   + 1024;       // 32 x 33
    float* s_A1  = s_wp  + 1056;       // 32 x 64  (early: sc 32x33)
    float* s_C1  = s_A1  + 2048;       // 32 x 64  (early: sp 32x33)
    float* s_Wst = s_C1  + 2048;       // 4096 floats: weight chunk buffer
    float* s_sc  = s_A1;
    float* s_sp  = s_C1;

    const int b = blockIdx.x;
    const int t = threadIdx.x;
    const int w = t >> 5, l = t & 31, r0 = 4 * w;

    const float* ac = actions  + (size_t)b * 1024;
    const float* po = policies + (size_t)b * 1024;

    // --- delta rows (pol - act) in registers, warp-local rows r0..r0+3 ---
    float d_r[4];
    #pragma unroll
    for (int r = 0; r < 4; ++r)
        d_r[r] = po[(r0 + r) * 32 + l] - ac[(r0 + r) * 32 + l];

    // --- load inputs ---
    {
        const float* st  = states         + (size_t)b * 32 * 96;
        const float* stp = states_people  + (size_t)b * 32 * 96;
        const float* acp = actions_people + (size_t)b * 1024;
        for (int idx = t; idx < 4096; idx += 256) {
            int i = idx >> 7, c = idx & 127;
            s_oa [i * 129 + c] = (c < 96) ? st [i * 96 + c] : ac [i * 32 + c - 96];
            s_oap[i * 129 + c] = (c < 96) ? stp[i * 96 + c] : acp[i * 32 + c - 96];
        }
    }

    // --- t = oa @ M (staged); scores -> sc ---
    {
        ull a1[4][2] = {{0,0},{0,0},{0,0},{0,0}};
        #pragma unroll 1
        for (int ck = 0; ck < 4; ++ck) {
            STAGE(g_M + ck * 4096);
            mm_chunk128(s_oa, 129, ck * 32, s_Wst, a1, r0, l);
        }
        store128(s_t, a1, r0, l, false);
        float a0 = 0, s1 = 0, s2 = 0, s3 = 0;
        #pragma unroll 4
        for (int f = 0; f < 128; ++f) {
            float oj = s_oa[l * 129 + f];
            a0 = fmaf(s_t[(r0 + 0) * 128 + f], oj, a0);
            s1 = fmaf(s_t[(r0 + 1) * 128 + f], oj, s1);
            s2 = fmaf(s_t[(r0 + 2) * 128 + f], oj, s2);
            s3 = fmaf(s_t[(r0 + 3) * 128 + f], oj, s3);
        }
        s_sc[(r0 + 0) * 33 + l] = a0;  s_sc[(r0 + 1) * 33 + l] = s1;
        s_sc[(r0 + 2) * 33 + l] = s2;  s_sc[(r0 + 3) * 33 + l] = s3;
    }

    // --- tp = oa @ Mp (staged); scores_p -> sp ---
    {
        ull a2[4][2] = {{0,0},{0,0},{0,0},{0,0}};
        #pragma unroll 1
        for (int ck = 0; ck < 4; ++ck) {
            STAGE(g_Mp + ck * 4096);
            mm_chunk128(s_oa, 129, ck * 32, s_Wst, a2, r0, l);
        }
        store128(s_t, a2, r0, l, false);
        float c0 = 0, c1 = 0, c2 = 0, c3 = 0;
        #pragma unroll 4
        for (int f = 0; f < 128; ++f) {
            float pj = s_oap[l * 129 + f];
            c0 = fmaf(s_t[(r0 + 0) * 128 + f], pj, c0);
            c1 = fmaf(s_t[(r0 + 1) * 128 + f], pj, c1);
            c2 = fmaf(s_t[(r0 + 2) * 128 + f], pj, c2);
            c3 = fmaf(s_t[(r0 + 3) * 128 + f], pj, c3);
        }
        s_sp[(r0 + 0) * 33 + l] = c0;  s_sp[(r0 + 1) * 33 + l] = c1;
        s_sp[(r0 + 2) * 33 + l] = c2;  s_sp[(r0 + 3) * 33 + l] = c3;
    }
    __syncthreads();   // sc/sp complete

    // --- column softmaxes ---
    {
        #pragma unroll
        for (int k = 0; k < 4; ++k) {
            int a = w + 8 * k;
            float v  = s_sc[l * 33 + a] * SOFTMAX_SCALE;
            float m  = warp_max(v);
            float e  = expf(v - m);
            float s  = warp_sum(e);
            float wg = e / s;
            s_w[a * 32 + l] = wg;
            out[WOFF + ((size_t)b * 32 + a) * 32 + l] = wg;
            float v2 = s_sp[l * 33 + a] * SOFTMAX_SCALE;
            float m2 = warp_max(v2);
            float e2 = expf(v2 - m2);
            float s2 = warp_sum(e2);
            s_wp[l * 33 + a] = e2 / s2;
        }
    }
    __syncthreads();   // frees sc/sp regions for A1/C1

    // === va -> A1 ; vp -> V(gmem) ; avp -> C1 (all weights staged) ===
    ull a1regs[4];     // A1 register copy for the V subtraction
    {
        // va = tanh(oa @ Wv)
        ull av[4][2] = {{0,0},{0,0},{0,0},{0,0}};
        #pragma unroll 1
        for (int ck = 0; ck < 4; ++ck) {
            STAGE(Wv + ck * 4096);
            mm_chunk128(s_oa, 129, ck * 32, s_Wst, av, r0, l);
        }
        ull va_pre[4][2];
        #pragma unroll
        for (int r = 0; r < 4; ++r) { va_pre[r][0] = av[r][0]; va_pre[r][1] = av[r][1]; }
        store128(s_t, av, r0, l, true);          // va rows (warp-local)

        // A1 = va @ Wf1_top
        {
            ull acc[4] = {0, 0, 0, 0};
            #pragma unroll 1
            for (int ck = 0; ck < 2; ++ck) {
                STAGE(Wf1 + ck * 4096);
                mm_chunk64(s_t, ck * 64, s_Wst, acc, r0, l);
            }
            #pragma unroll
            for (int r = 0; r < 4; ++r) {
                a1regs[r] = acc[r];
                *reinterpret_cast<float2*>(&s_A1[(r0 + r) * 64 + 2 * l]) = upk2(acc[r]);
            }
        }

        // vp = tanh(va_pre + (pol-act) @ Wv[96:,:])  (staged chunk, shfl X)
        {
            STAGE(Wv + 96 * 128);
            #pragma unroll 4
            for (int e = 0; e < 32; ++e) {
                ulonglong2 wv = *reinterpret_cast<const ulonglong2*>(&s_Wst[e * 128 + 4 * l]);
                #pragma unroll
                for (int r = 0; r < 4; ++r) {
                    ull xx = pk2(__shfl_sync(0xffffffffu, d_r[r], e));
                    va_pre[r][0] = ffma2(xx, wv.x, va_pre[r][0]);
                    va_pre[r][1] = ffma2(xx, wv.y, va_pre[r][1]);
                }
            }
            store128(s_t, va_pre, r0, l, true);  // vp rows
        }

        // V = (vp @ Wf1_top - A1) / 32 -> gmem
        {
            ull acc[4] = {0, 0, 0, 0};
            #pragma unroll 1
            for (int ck = 0; ck < 2; ++ck) {
                STAGE(Wf1 + ck * 4096);
                mm_chunk64(s_t, ck * 64, s_Wst, acc, r0, l);
            }
            float* gV = g_V + (size_t)b * 2048;
            #pragma unroll
            for (int r = 0; r < 4; ++r) {
                float2 p = upk2(acc[r]);
                float2 a = upk2(a1regs[r]);
                *reinterpret_cast<float2*>(&gV[(r0 + r) * 64 + 2 * l]) =
                    make_float2((p.x - a.x) * 0.03125f, (p.y - a.y) * 0.03125f);
            }
        }

        // avp = tanh(oap @ Wvp) ; C1 = avp @ Wf1_bot
        {
            ull ap[4][2] = {{0,0},{0,0},{0,0},{0,0}};
            #pragma unroll 1
            for (int ck = 0; ck < 4; ++ck) {
                STAGE(Wvp + ck * 4096);
                mm_chunk128(s_oap, 129, ck * 32, s_Wst, ap, r0, l);
            }
            store128(s_t, ap, r0, l, true);
            ull acc[4] = {0, 0, 0, 0};
            #pragma unroll 1
            for (int ck = 0; ck < 2; ++ck) {
                STAGE(Wf1 + 8192 + ck * 4096);
                mm_chunk64(s_t, ck * 64, s_Wst, acc, r0, l);
            }
            #pragma unroll
            for (int r = 0; r < 4; ++r)
                *reinterpret_cast<float2*>(&s_C1[(r0 + r) * 64 + 2 * l]) = upk2(acc[r]);
        }
    }
    __syncthreads();   // A1/C1 complete (cross-warp reads next)

    // --- wp to global ---
    for (int idx = t; idx < 1024; idx += 256)
        out[WPOFF + (size_t)b * 1024 + idx] = s_wp[(idx >> 5) * 33 + (idx & 31)];

    // --- U[a, 2l..2l+1] = (w[a,:]@A1 + wp[a,:]@C1)/32, warp rows r0..r0+3 ---
    {
        const ull* A1u = reinterpret_cast<const ull*>(s_A1);
        const ull* C1u = reinterpret_cast<const ull*>(s_C1);
        ull uacc[4] = {0, 0, 0, 0};
        #pragma unroll 4
        for (int j = 0; j < 32; ++j) {
            ull wv = A1u[j * 32 + l];
            #pragma unroll
            for (int r = 0; r < 4; ++r)
                uacc[r] = ffma2(pk2(s_w[(r0 + r) * 32 + j]), wv, uacc[r]);
        }
        #pragma unroll 4
        for (int p = 0; p < 32; ++p) {
            ull wv = C1u[p * 32 + l];
            #pragma unroll
            for (int r = 0; r < 4; ++r)
                uacc[r] = ffma2(pk2(s_wp[(r0 + r) * 33 + p]), wv, uacc[r]);
        }
        float* gU = g_U + (size_t)b * 2048;
        #pragma unroll
        for (int r = 0; r < 4; ++r) {
            float2 p = upk2(uacc[r]);
            *reinterpret_cast<float2*>(&gU[(r0 + r) * 64 + 2 * l]) =
                make_float2(p.x * 0.03125f, p.y * 0.03125f);
        }
    }
}

// ---------------------------------------------------------------------------
// Kernel 2 (round-2/4 proven): value = lrelu(U + weight*V) @ W_f2
// ---------------------------------------------------------------------------
extern "C" __global__ void __launch_bounds__(256)
k2_value(const float* __restrict__ Wf2, float* __restrict__ out) {
    __shared__ float sU [8 * 64];
    __shared__ float sV [32 * 65];
    __shared__ __align__(16) float sW2[64 * 32];
    __shared__ float sW [8 * 33];
    const int t  = threadIdx.x;
    const int b  = blockIdx.x >> 2;
    const int a0 = (blockIdx.x & 3) * 8;

    for (int idx = t; idx < 2048; idx += 256) {
        int i = idx >> 6, f = idx & 63;
        sV[i * 65 + f] = g_V[(size_t)b * 2048 + idx];
    }
    for (int idx = t; idx < 512; idx += 256)
        sU[idx] = g_U[(size_t)b * 2048 + a0 * 64 + idx];
    for (int idx = t; idx < 2048; idx += 256) sW2[idx] = Wf2[idx];
    {
        int a = t >> 5, i = t & 31;
        sW[a * 33 + i] = out[WOFF + ((size_t)b * 32 + a0 + a) * 32 + i];
    }
    __syncthreads();

    const int w = t >> 5, l = t & 31;
    const float wai = sW[w * 33 + l];
    const float* Ua = &sU[w * 64];
    ull acc[16];
    #pragma unroll
    for (int q = 0; q < 16; ++q) acc[q] = 0ull;

    #pragma unroll 8
    for (int f = 0; f < 64; ++f) {
        float h = fmaf(wai, sV[l * 65 + f], Ua[f]);
        h = fmaxf(h, 0.f) + 0.01f * fminf(h, 0.f);       // leaky_relu(0.01)
        ull hh = pk2(h);
        const ulonglong2* row = reinterpret_cast<const ulonglong2*>(&sW2[f * 32]);
        #pragma unroll
        for (int q = 0; q < 8; ++q) {
            ulonglong2 wv = row[q];
            acc[2 * q]     = ffma2(hh, wv.x, acc[2 * q]);
            acc[2 * q + 1] = ffma2(hh, wv.y, acc[2 * q + 1]);
        }
    }
    float4* op = reinterpret_cast<float4*>(out + (((size_t)b * 32 + a0 + w) * 32 + l) * 32);
    #pragma unroll
    for (int q = 0; q < 8; ++q) {
        float2 p0 = upk2(acc[2 * q]);
        float2 p1 = upk2(acc[2 * q + 1]);
        op[q] = make_float4(p0.x, p0.y, p1.x, p1.y);
    }
}

// ---------------------------------------------------------------------------
extern "C" void kernel_launch(void* const* d_in, const int* in_sizes, int n_in,
                              void* d_out, int out_size) {
    const float* states         = (const float*)d_in[0];
    const float* policies       = (const float*)d_in[1];
    const float* actions        = (const float*)d_in[2];
    const float* states_people  = (const float*)d_in[3];
    const float* actions_people = (const float*)d_in[4];
    const float* Wk  = (const float*)d_in[5];
    const float* Wq  = (const float*)d_in[6];
    const float* Wv  = (const float*)d_in[7];
    const float* Wkp = (const float*)d_in[8];
    const float* Wqp = (const float*)d_in[9];
    const float* Wvp = (const float*)d_in[10];
    const float* Wf1 = (const float*)d_in[11];
    const float* Wf2 = (const float*)d_in[12];
    float* out = (float*)d_out;

    k0_precompute<<<dim3(16, 2, 2), 256>>>(Wq, Wk, Wqp, Wkp);

    cudaFuncSetAttribute(k1_batch, cudaFuncAttributeMaxDynamicSharedMemorySize, SM1_BYTES);
    k1_batch<<<256, 256, SM1_BYTES>>>(states, policies, actions,
                                      states_people, actions_people,
                                      Wv, Wvp, Wf1, out);

    k2_value<<<1024, 256>>>(Wf2, out);
}

// round 7
// speedup vs baseline: 1.6055x; 1.1762x over previous
#include <cuda_runtime.h>
#include <math.h>

#define BB   256

// out layout: value [B,32,32,32] | weight [B,32,32] | wp [B,32,32]
#define WOFF      (8388608ull)
#define WPOFF     (8650752ull)

typedef unsigned long long ull;

__device__ float g_M [128 * 128];
__device__ float g_Mp[128 * 128];
__device__ float g_U [BB * 32 * 64];
__device__ float g_V [BB * 32 * 64];

// ---- packed f32x2 helpers ----
__device__ __forceinline__ ull pk2(float v) {
    ull r; asm("mov.b64 %0, {%1, %1};" : "=l"(r) : "f"(v)); return r;
}
__device__ __forceinline__ ull ffma2(ull a, ull b, ull c) {
    ull d; asm("fma.rn.f32x2 %0, %1, %2, %3;" : "=l"(d) : "l"(a), "l"(b), "l"(c)); return d;
}
__device__ __forceinline__ float2 upk2(ull v) {
    float2 f; asm("mov.b64 {%0, %1}, %2;" : "=f"(f.x), "=f"(f.y) : "l"(v)); return f;
}

// ---- tf32 helpers ----
__device__ __forceinline__ unsigned tf32_of(float x) {
    unsigned r; asm("cvt.rna.tf32.f32 %0, %1;" : "=r"(r) : "f"(x)); return r;
}
__device__ __forceinline__ void mma_tf32(float d[4], const unsigned a[4],
                                         unsigned b0, unsigned b1) {
    asm("mma.sync.aligned.m16n8k8.row.col.f32.tf32.tf32.f32 "
        "{%0,%1,%2,%3}, {%4,%5,%6,%7}, {%8,%9}, {%0,%1,%2,%3};"
        : "+f"(d[0]), "+f"(d[1]), "+f"(d[2]), "+f"(d[3])
        : "r"(a[0]), "r"(a[1]), "r"(a[2]), "r"(a[3]), "r"(b0), "r"(b1));
}

__device__ __forceinline__ float warp_max(float v) {
    #pragma unroll
    for (int o = 16; o; o >>= 1) v = fmaxf(v, __shfl_xor_sync(0xffffffffu, v, o));
    return v;
}
__device__ __forceinline__ float warp_sum(float v) {
    #pragma unroll
    for (int o = 16; o; o >>= 1) v += __shfl_xor_sync(0xffffffffu, v, o);
    return v;
}

// ---------------------------------------------------------------------------
// Kernel 0 (unchanged): M = W_q @ W_k^T, Mp = W_qp @ W_kp^T
// ---------------------------------------------------------------------------
__global__ void k0_precompute(const float* __restrict__ Wq, const float* __restrict__ Wk,
                              const float* __restrict__ Wqp, const float* __restrict__ Wkp) {
    __shared__ float sA[8 * 128];
    __shared__ float sB[64 * 129];
    const float* A  = blockIdx.z ? Wqp : Wq;
    const float* Bm = blockIdx.z ? Wkp : Wk;
    float* out      = blockIdx.z ? g_Mp : g_M;
    const int e0 = blockIdx.x * 8;
    const int c0 = blockIdx.y * 64;
    const int t  = threadIdx.x;
    for (int idx = t; idx < 1024; idx += 256) sA[idx] = A[e0 * 128 + idx];
    for (int idx = t; idx < 64 * 128; idx += 256) {
        int r = idx >> 7, d = idx & 127;
        sB[r * 129 + d] = Bm[(c0 + r) * 128 + d];
    }
    __syncthreads();
    const int w = t >> 5, l = t & 31;
    float a0 = 0.f, a1 = 0.f;
    #pragma unroll 8
    for (int d = 0; d < 128; ++d) {
        float av = sA[w * 128 + d];
        a0 = fmaf(av, sB[l * 129 + d], a0);
        a1 = fmaf(av, sB[(l + 32) * 129 + d], a1);
    }
    out[(e0 + w) * 128 + c0 + l]      = a0;
    out[(e0 + w) * 128 + c0 + 32 + l] = a1;
}

// ---------------------------------------------------------------------------
// k1 staged GEMM cores (unchanged from round 6)
// ---------------------------------------------------------------------------
__device__ __forceinline__ void mm_chunk128(const float* __restrict__ X, int xstr, int e0,
                                            const float* __restrict__ Ws,
                                            ull acc[4][2], int r0, int l) {
    #pragma unroll 4
    for (int e = 0; e < 32; ++e) {
        ulonglong2 wv = *reinterpret_cast<const ulonglong2*>(&Ws[e * 128 + 4 * l]);
        #pragma unroll
        for (int r = 0; r < 4; ++r) {
            ull xx = pk2(X[(r0 + r) * xstr + e0 + e]);
            acc[r][0] = ffma2(xx, wv.x, acc[r][0]);
            acc[r][1] = ffma2(xx, wv.y, acc[r][1]);
        }
    }
}

__device__ __forceinline__ void mm_chunk64(const float* __restrict__ X, int e0,
                                           const float* __restrict__ Ws,
                                           ull acc[4], int r0, int l) {
    #pragma unroll 4
    for (int e = 0; e < 64; ++e) {
        ull wv = *reinterpret_cast<const ull*>(&Ws[e * 64 + 2 * l]);
        #pragma unroll
        for (int r = 0; r < 4; ++r)
            acc[r] = ffma2(pk2(X[(r0 + r) * 128 + e0 + e]), wv, acc[r]);
    }
}

__device__ __forceinline__ void store128(float* __restrict__ Y, ull acc[4][2],
                                         int r0, int l, bool do_tanh) {
    #pragma unroll
    for (int r = 0; r < 4; ++r) {
        float2 p0 = upk2(acc[r][0]);
        float2 p1 = upk2(acc[r][1]);
        float4 v = make_float4(p0.x, p0.y, p1.x, p1.y);
        if (do_tanh) { v.x = tanhf(v.x); v.y = tanhf(v.y); v.z = tanhf(v.z); v.w = tanhf(v.w); }
        *reinterpret_cast<float4*>(&Y[(r0 + r) * 128 + 4 * l]) = v;
    }
}

// ---------------------------------------------------------------------------
// Kernel 1: one block per batch (unchanged from round 6). smem 90,496 B.
// ---------------------------------------------------------------------------
#define SM1_BYTES 90496
#define SOFTMAX_SCALE 0.08838834764831843f   // 1/sqrt(128)

#define STAGE(SRC) do {                                                    \
    __syncthreads();                                                       \
    { const float4* s4 = reinterpret_cast<const float4*>(SRC);            \
      float4* d4 = reinterpret_cast<float4*>(s_Wst);                      \
      for (int i = t; i < 1024; i += 256) d4[i] = s4[i]; }                \
    __syncthreads();                                                       \
} while (0)

extern "C" __global__ void __launch_bounds__(256, 2)
k1_batch(const float* __restrict__ states, const float* __restrict__ policies,
         const float* __restrict__ actions, const float* __restrict__ states_people,
         const float* __restrict__ actions_people,
         const float* __restrict__ Wv, const float* __restrict__ Wvp,
         const float* __restrict__ Wf1, float* __restrict__ out) {
    extern __shared__ __align__(16) float sm[];
    float* s_oa  = sm;                 // 32 x 129
    float* s_oap = s_oa  + 4128;       // 32 x 129
    float* s_t   = s_oap + 4128;       // 32 x 128
    float* s_w   = s_t   + 4096;       // 32 x 32
    float* s_wp  = s_w   + 1024;       // 32 x 33
    float* s_A1  = s_wp  + 1056;       // 32 x 64  (early: sc 32x33)
    float* s_C1  = s_A1  + 2048;       // 32 x 64  (early: sp 32x33)
    float* s_Wst = s_C1  + 2048;       // 4096 floats: weight chunk buffer
    float* s_sc  = s_A1;
    float* s_sp  = s_C1;

    const int b = blockIdx.x;
    const int t = threadIdx.x;
    const int w = t >> 5, l = t & 31, r0 = 4 * w;

    const float* ac = actions  + (size_t)b * 1024;
    const float* po = policies + (size_t)b * 1024;

    float d_r[4];
    #pragma unroll
    for (int r = 0; r < 4; ++r)
        d_r[r] = po[(r0 + r) * 32 + l] - ac[(r0 + r) * 32 + l];

    {
        const float* st  = states         + (size_t)b * 32 * 96;
        const float* stp = states_people  + (size_t)b * 32 * 96;
        const float* acp = actions_people + (size_t)b * 1024;
        for (int idx = t; idx < 4096; idx += 256) {
            int i = idx >> 7, c = idx & 127;
            s_oa [i * 129 + c] = (c < 96) ? st [i * 96 + c] : ac [i * 32 + c - 96];
            s_oap[i * 129 + c] = (c < 96) ? stp[i * 96 + c] : acp[i * 32 + c - 96];
        }
    }

    // --- t = oa @ M (staged); scores -> sc ---
    {
        ull a1[4][2] = {{0,0},{0,0},{0,0},{0,0}};
        #pragma unroll 1
        for (int ck = 0; ck < 4; ++ck) {
            STAGE(g_M + ck * 4096);
            mm_chunk128(s_oa, 129, ck * 32, s_Wst, a1, r0, l);
        }
        store128(s_t, a1, r0, l, false);
        float a0 = 0, s1 = 0, s2 = 0, s3 = 0;
        #pragma unroll 4
        for (int f = 0; f < 128; ++f) {
            float oj = s_oa[l * 129 + f];
            a0 = fmaf(s_t[(r0 + 0) * 128 + f], oj, a0);
            s1 = fmaf(s_t[(r0 + 1) * 128 + f], oj, s1);
            s2 = fmaf(s_t[(r0 + 2) * 128 + f], oj, s2);
            s3 = fmaf(s_t[(r0 + 3) * 128 + f], oj, s3);
        }
        s_sc[(r0 + 0) * 33 + l] = a0;  s_sc[(r0 + 1) * 33 + l] = s1;
        s_sc[(r0 + 2) * 33 + l] = s2;  s_sc[(r0 + 3) * 33 + l] = s3;
    }

    // --- tp = oa @ Mp (staged); scores_p -> sp ---
    {
        ull a2[4][2] = {{0,0},{0,0},{0,0},{0,0}};
        #pragma unroll 1
        for (int ck = 0; ck < 4; ++ck) {
            STAGE(g_Mp + ck * 4096);
            mm_chunk128(s_oa, 129, ck * 32, s_Wst, a2, r0, l);
        }
        store128(s_t, a2, r0, l, false);
        float c0 = 0, c1 = 0, c2 = 0, c3 = 0;
        #pragma unroll 4
        for (int f = 0; f < 128; ++f) {
            float pj = s_oap[l * 129 + f];
            c0 = fmaf(s_t[(r0 + 0) * 128 + f], pj, c0);
            c1 = fmaf(s_t[(r0 + 1) * 128 + f], pj, c1);
            c2 = fmaf(s_t[(r0 + 2) * 128 + f], pj, c2);
            c3 = fmaf(s_t[(r0 + 3) * 128 + f], pj, c3);
        }
        s_sp[(r0 + 0) * 33 + l] = c0;  s_sp[(r0 + 1) * 33 + l] = c1;
        s_sp[(r0 + 2) * 33 + l] = c2;  s_sp[(r0 + 3) * 33 + l] = c3;
    }
    __syncthreads();

    // --- column softmaxes ---
    {
        #pragma unroll
        for (int k = 0; k < 4; ++k) {
            int a = w + 8 * k;
            float v  = s_sc[l * 33 + a] * SOFTMAX_SCALE;
            float m  = warp_max(v);
            float e  = expf(v - m);
            float s  = warp_sum(e);
            float wg = e / s;
            s_w[a * 32 + l] = wg;
            out[WOFF + ((size_t)b * 32 + a) * 32 + l] = wg;
            float v2 = s_sp[l * 33 + a] * SOFTMAX_SCALE;
            float m2 = warp_max(v2);
            float e2 = expf(v2 - m2);
            float s2 = warp_sum(e2);
            s_wp[l * 33 + a] = e2 / s2;
        }
    }
    __syncthreads();

    // === va -> A1 ; vp -> V(gmem) ; avp -> C1 ===
    ull a1regs[4];
    {
        ull av[4][2] = {{0,0},{0,0},{0,0},{0,0}};
        #pragma unroll 1
        for (int ck = 0; ck < 4; ++ck) {
            STAGE(Wv + ck * 4096);
            mm_chunk128(s_oa, 129, ck * 32, s_Wst, av, r0, l);
        }
        ull va_pre[4][2];
        #pragma unroll
        for (int r = 0; r < 4; ++r) { va_pre[r][0] = av[r][0]; va_pre[r][1] = av[r][1]; }
        store128(s_t, av, r0, l, true);

        {
            ull acc[4] = {0, 0, 0, 0};
            #pragma unroll 1
            for (int ck = 0; ck < 2; ++ck) {
                STAGE(Wf1 + ck * 4096);
                mm_chunk64(s_t, ck * 64, s_Wst, acc, r0, l);
            }
            #pragma unroll
            for (int r = 0; r < 4; ++r) {
                a1regs[r] = acc[r];
                *reinterpret_cast<float2*>(&s_A1[(r0 + r) * 64 + 2 * l]) = upk2(acc[r]);
            }
        }

        {
            STAGE(Wv + 96 * 128);
            #pragma unroll 4
            for (int e = 0; e < 32; ++e) {
                ulonglong2 wv = *reinterpret_cast<const ulonglong2*>(&s_Wst[e * 128 + 4 * l]);
                #pragma unroll
                for (int r = 0; r < 4; ++r) {
                    ull xx = pk2(__shfl_sync(0xffffffffu, d_r[r], e));
                    va_pre[r][0] = ffma2(xx, wv.x, va_pre[r][0]);
                    va_pre[r][1] = ffma2(xx, wv.y, va_pre[r][1]);
                }
            }
            store128(s_t, va_pre, r0, l, true);
        }

        {
            ull acc[4] = {0, 0, 0, 0};
            #pragma unroll 1
            for (int ck = 0; ck < 2; ++ck) {
                STAGE(Wf1 + ck * 4096);
                mm_chunk64(s_t, ck * 64, s_Wst, acc, r0, l);
            }
            float* gV = g_V + (size_t)b * 2048;
            #pragma unroll
            for (int r = 0; r < 4; ++r) {
                float2 p = upk2(acc[r]);
                float2 a = upk2(a1regs[r]);
                *reinterpret_cast<float2*>(&gV[(r0 + r) * 64 + 2 * l]) =
                    make_float2((p.x - a.x) * 0.03125f, (p.y - a.y) * 0.03125f);
            }
        }

        {
            ull ap[4][2] = {{0,0},{0,0},{0,0},{0,0}};
            #pragma unroll 1
            for (int ck = 0; ck < 4; ++ck) {
                STAGE(Wvp + ck * 4096);
                mm_chunk128(s_oap, 129, ck * 32, s_Wst, ap, r0, l);
            }
            store128(s_t, ap, r0, l, true);
            ull acc[4] = {0, 0, 0, 0};
            #pragma unroll 1
            for (int ck = 0; ck < 2; ++ck) {
                STAGE(Wf1 + 8192 + ck * 4096);
                mm_chunk64(s_t, ck * 64, s_Wst, acc, r0, l);
            }
            #pragma unroll
            for (int r = 0; r < 4; ++r)
                *reinterpret_cast<float2*>(&s_C1[(r0 + r) * 64 + 2 * l]) = upk2(acc[r]);
        }
    }
    __syncthreads();

    for (int idx = t; idx < 1024; idx += 256)
        out[WPOFF + (size_t)b * 1024 + idx] = s_wp[(idx >> 5) * 33 + (idx & 31)];

    {
        const ull* A1u = reinterpret_cast<const ull*>(s_A1);
        const ull* C1u = reinterpret_cast<const ull*>(s_C1);
        ull uacc[4] = {0, 0, 0, 0};
        #pragma unroll 4
        for (int j = 0; j < 32; ++j) {
            ull wv = A1u[j * 32 + l];
            #pragma unroll
            for (int r = 0; r < 4; ++r)
                uacc[r] = ffma2(pk2(s_w[(r0 + r) * 32 + j]), wv, uacc[r]);
        }
        #pragma unroll 4
        for (int p = 0; p < 32; ++p) {
            ull wv = C1u[p * 32 + l];
            #pragma unroll
            for (int r = 0; r < 4; ++r)
                uacc[r] = ffma2(pk2(s_wp[(r0 + r) * 33 + p]), wv, uacc[r]);
        }
        float* gU = g_U + (size_t)b * 2048;
        #pragma unroll
        for (int r = 0; r < 4; ++r) {
            float2 p = upk2(uacc[r]);
            *reinterpret_cast<float2*>(&gU[(r0 + r) * 64 + 2 * l]) =
                make_float2(p.x * 0.03125f, p.y * 0.03125f);
        }
    }
}

// ---------------------------------------------------------------------------
// Kernel 2 (NEW): tensor-core 3xTF32 value GEMM.
// grid 1024 = (b, a-quad of 8); warp w -> a = a0 + w.
// Per warp: H[32 i, 64 f] @ W2[64 f, 32 n] via m16n8k8 tiles (2m x 4n x 8k),
// 3 MMAs per tile (Ah*Bh + Ah*Bl + Al*Bh). H built per-lane in fragment layout.
// ---------------------------------------------------------------------------
extern "C" __global__ void __launch_bounds__(256)
k2_value(const float* __restrict__ Wf2, float* __restrict__ out) {
    __shared__ float    sV [32 * 68];    // V[i][f], stride 68 (conflict-free quad reads)
    __shared__ float    sU [8 * 64];     // U[a'][f]
    __shared__ float    swt[8 * 32];     // weight[a'][i]
    __shared__ unsigned sW2h[64 * 36];   // tf32(W2)[f][n], stride 36
    __shared__ unsigned sW2l[64 * 36];   // tf32(W2 - hi)

    const int t  = threadIdx.x;
    const int b  = blockIdx.x >> 2;
    const int a0 = (blockIdx.x & 3) * 8;

    for (int idx = t; idx < 2048; idx += 256) {
        int i = idx >> 6, f = idx & 63;
        sV[i * 68 + f] = g_V[(size_t)b * 2048 + idx];
    }
    for (int idx = t; idx < 512; idx += 256)
        sU[idx] = g_U[(size_t)b * 2048 + a0 * 64 + idx];
    {
        int a = t >> 5, i = t & 31;
        swt[a * 32 + i] = out[WOFF + ((size_t)b * 32 + a0 + a) * 32 + i];
    }
    for (int idx = t; idx < 2048; idx += 256) {
        int f = idx >> 5, n = idx & 31;
        float v = Wf2[idx];
        unsigned hb = tf32_of(v);
        sW2h[f * 36 + n] = hb;
        sW2l[f * 36 + n] = tf32_of(v - __uint_as_float(hb));
    }
    __syncthreads();

    const int w = t >> 5, l = t & 31;
    const int lq = l >> 2;            // 0..7  (fragment row group)
    const int lr = l & 3;             // 0..3  (fragment col group)
    const float* Urow = &sU [w * 64];
    const float* wrow = &swt[w * 32];

    // preload U (by f) and weight (by i) fragment scalars
    float Uf[8][2];
    #pragma unroll
    for (int kt = 0; kt < 8; ++kt) {
        Uf[kt][0] = Urow[kt * 8 + lr];
        Uf[kt][1] = Urow[kt * 8 + lr + 4];
    }
    float wm[2][2];
    #pragma unroll
    for (int mt = 0; mt < 2; ++mt) {
        wm[mt][0] = wrow[mt * 16 + lq];
        wm[mt][1] = wrow[mt * 16 + lq + 8];
    }

    float D[2][4][4];
    #pragma unroll
    for (int mt = 0; mt < 2; ++mt)
        #pragma unroll
        for (int nt = 0; nt < 4; ++nt)
            #pragma unroll
            for (int q = 0; q < 4; ++q) D[mt][nt][q] = 0.f;

    #pragma unroll
    for (int kt = 0; kt < 8; ++kt) {
        const int f1 = kt * 8 + lr;
        unsigned Ah[2][4], Al[2][4];
        #pragma unroll
        for (int mt = 0; mt < 2; ++mt) {
            const int i1 = mt * 16 + lq;
            float v00 = sV[i1 * 68 + f1];
            float v10 = sV[(i1 + 8) * 68 + f1];
            float v01 = sV[i1 * 68 + f1 + 4];
            float v11 = sV[(i1 + 8) * 68 + f1 + 4];
            float h0 = fmaf(wm[mt][0], v00, Uf[kt][0]);
            float h1 = fmaf(wm[mt][1], v10, Uf[kt][0]);
            float h2 = fmaf(wm[mt][0], v01, Uf[kt][1]);
            float h3 = fmaf(wm[mt][1], v11, Uf[kt][1]);
            h0 = fmaxf(h0, 0.f) + 0.01f * fminf(h0, 0.f);
            h1 = fmaxf(h1, 0.f) + 0.01f * fminf(h1, 0.f);
            h2 = fmaxf(h2, 0.f) + 0.01f * fminf(h2, 0.f);
            h3 = fmaxf(h3, 0.f) + 0.01f * fminf(h3, 0.f);
            Ah[mt][0] = tf32_of(h0);
            Ah[mt][1] = tf32_of(h1);
            Ah[mt][2] = tf32_of(h2);
            Ah[mt][3] = tf32_of(h3);
            Al[mt][0] = tf32_of(h0 - __uint_as_float(Ah[mt][0]));
            Al[mt][1] = tf32_of(h1 - __uint_as_float(Ah[mt][1]));
            Al[mt][2] = tf32_of(h2 - __uint_as_float(Ah[mt][2]));
            Al[mt][3] = tf32_of(h3 - __uint_as_float(Ah[mt][3]));
        }
        #pragma unroll
        for (int nt = 0; nt < 4; ++nt) {
            const int bo = f1 * 36 + nt * 8 + lq;
            unsigned b0h = sW2h[bo], b1h = sW2h[bo + 4 * 36];
            unsigned b0l = sW2l[bo], b1l = sW2l[bo + 4 * 36];
            #pragma unroll
            for (int mt = 0; mt < 2; ++mt) {
                mma_tf32(D[mt][nt], Ah[mt], b0h, b1h);
                mma_tf32(D[mt][nt], Ah[mt], b0l, b1l);
                mma_tf32(D[mt][nt], Al[mt], b0h, b1h);
            }
        }
    }

    // epilogue: D frag (c0,c1)=(row lq, cols 2lr,2lr+1), (c2,c3)=(row lq+8, ...)
    const size_t base = (((size_t)b * 32) + a0 + w) * 1024;
    #pragma unroll
    for (int mt = 0; mt < 2; ++mt) {
        #pragma unroll
        for (int nt = 0; nt < 4; ++nt) {
            const int i1 = mt * 16 + lq;
            const int n  = nt * 8 + 2 * lr;
            *reinterpret_cast<float2*>(&out[base + i1 * 32 + n]) =
                make_float2(D[mt][nt][0], D[mt][nt][1]);
            *reinterpret_cast<float2*>(&out[base + (i1 + 8) * 32 + n]) =
                make_float2(D[mt][nt][2], D[mt][nt][3]);
        }
    }
}

// ---------------------------------------------------------------------------
extern "C" void kernel_launch(void* const* d_in, const int* in_sizes, int n_in,
                              void* d_out, int out_size) {
    const float* states         = (const float*)d_in[0];
    const float* policies       = (const float*)d_in[1];
    const float* actions        = (const float*)d_in[2];
    const float* states_people  = (const float*)d_in[3];
    const float* actions_people = (const float*)d_in[4];
    const float* Wk  = (const float*)d_in[5];
    const float* Wq  = (const float*)d_in[6];
    const float* Wv  = (const float*)d_in[7];
    const float* Wkp = (const float*)d_in[8];
    const float* Wqp = (const float*)d_in[9];
    const float* Wvp = (const float*)d_in[10];
    const float* Wf1 = (const float*)d_in[11];
    const float* Wf2 = (const float*)d_in[12];
    float* out = (float*)d_out;

    k0_precompute<<<dim3(16, 2, 2), 256>>>(Wq, Wk, Wqp, Wkp);

    cudaFuncSetAttribute(k1_batch, cudaFuncAttributeMaxDynamicSharedMemorySize, SM1_BYTES);
    k1_batch<<<256, 256, SM1_BYTES>>>(states, policies, actions,
                                      states_people, actions_people,
                                      Wv, Wvp, Wf1, out);

    k2_value<<<1024, 256>>>(Wf2, out);
}